// round 6
// baseline (speedup 1.0000x reference)
#include <cuda_runtime.h>
#include <cuda_bf16.h>
#include <stdint.h>

#define KTOT 1024
#define DIM  64
#define HW   4096
#define QELEMS 4194304
#define DELTA 2.5e-3f
#define CAP  24
#define INF __int_as_float(0x7f800000)

// dynamic smem offsets (bytes)
#define XS_OFF 0        // f32 xs[64][128]              32768
#define B_OFF  32768    // bf16 B[256][72] padded       36864
#define CN_OFF 69632    // f32 cn[256]                   1024
#define CD_OFF 70656    // u16 cdL[256][CAP]            12288
#define XN_OFF 82944    // f32 xn[128]                    512
#define RM_OFF 83456    // u64 rmin[128][2]              2048
#define SI_OFF 85504    // i32 sidx[128]                  512
#define LR_OFF 86016    // f32 lred[256]                 1024
#define SMEM_BYTES 87040

__device__ float g_cnorm[KTOT];
__device__ __align__(16) __nv_bfloat16 g_cbb[KTOT*DIM];

__global__ void vq_prep(const float* __restrict__ cb, float* __restrict__ loss_ptr){
    int k = blockIdx.x*256 + threadIdx.x;
    if (k==0) *loss_ptr = 0.0f;
    if (k < KTOT){
        float s = 0.0f;
        #pragma unroll
        for (int d=0; d<DIM; ++d){
            float c = cb[k*DIM+d];
            g_cbb[k*DIM+d] = __float2bfloat16(c);
            s = __fadd_rn(s, __fmul_rn(c,c));
        }
        g_cnorm[k] = s;
    }
}

__device__ __forceinline__ uint32_t packbf(float lo, float hi){
    __nv_bfloat162 h = __floats2bfloat162_rn(lo, hi);
    return *(uint32_t*)&h;
}
__device__ __forceinline__ uint32_t f2o(float f){
    uint32_t u = __float_as_uint(f);
    return (u & 0x80000000u) ? ~u : (u | 0x80000000u);
}

__global__ void __launch_bounds__(256,2) vq_hmma_kernel(
    const float* __restrict__ x, const float* __restrict__ cb,
    float* __restrict__ out, float* __restrict__ loss_ptr)
{
    extern __shared__ char smc[];
    float*              xs  = (float*)(smc + XS_OFF);
    __nv_bfloat16*      Bs  = (__nv_bfloat16*)(smc + B_OFF);
    float*              cns = (float*)(smc + CN_OFF);
    uint16_t*           cdL = (uint16_t*)(smc + CD_OFF);
    float*              xns = (float*)(smc + XN_OFF);
    unsigned long long* rmn = (unsigned long long*)(smc + RM_OFF);
    int*                sid = (int*)(smc + SI_OFF);
    float*              lrd = (float*)(smc + LR_OFF);

    const int tid = threadIdx.x;
    const int b = blockIdx.x>>5, h0 = (blockIdx.x&31)*2;

    // ---- load x tile [d][m] (coalesced over w) ----
    {
        int w=tid&63, hh=(tid>>6)&1, dh=(tid>>7)*32, m=hh*64+w;
        const float* xb = x + (size_t)b*DIM*HW + (size_t)(h0+hh)*64 + w;
        #pragma unroll
        for (int i=0;i<32;i++){ int d=dh+i; xs[d*128+m] = xb[(size_t)d*HW]; }
    }
    __syncthreads();

    // ---- per-row ||x||^2 (mul/add, ascending d) ----
    if (tid<128){
        float s=0.0f;
        #pragma unroll
        for (int d=0; d<DIM; ++d){ float v=xs[d*128+tid]; s=__fadd_rn(s,__fmul_rn(v,v)); }
        xns[tid]=s;
    }

    const int lane = tid&31, w = tid>>5;
    const int g = lane>>2, tg = lane&3;
    const int mbase = (w&3)*32, nhalf = w>>2;
    const int R[4] = { mbase+g, mbase+8+g, mbase+16+g, mbase+24+g };

    // ---- A fragments once (m16n8k16 row-major layout) ----
    uint32_t afr[2][4][4];
    #pragma unroll
    for (int mt=0; mt<2; ++mt)
        #pragma unroll
        for (int ks=0; ks<4; ++ks){
            int R0 = mbase + mt*16 + g, R1 = R0 + 8;
            int c0 = ks*16 + 2*tg, c2 = c0 + 8;
            afr[mt][ks][0] = packbf(xs[c0*128+R0], xs[(c0+1)*128+R0]);
            afr[mt][ks][1] = packbf(xs[c0*128+R1], xs[(c0+1)*128+R1]);
            afr[mt][ks][2] = packbf(xs[c2*128+R0], xs[(c2+1)*128+R0]);
            afr[mt][ks][3] = packbf(xs[c2*128+R1], xs[(c2+1)*128+R1]);
        }

    float runmin[4] = {INF,INF,INF,INF};
    int cnt = 0;

    for (int ch=0; ch<4; ++ch){
        // ---- load B chunk (256 rows x 64 bf16 = 2048 uint4) + cn chunk ----
        {
            const uint4* src = ((const uint4*)g_cbb) + ch*2048;
            #pragma unroll
            for (int j=tid; j<2048; j+=256){
                int row=j>>3, part=j&7;
                *(uint4*)(Bs + row*72 + part*8) = src[j];
            }
            cns[tid] = g_cnorm[ch*256+tid];
        }
        __syncthreads();

        #pragma unroll 1
        for (int nt=0; nt<16; ++nt){
            int n0 = nhalf*128 + nt*8;
            float2 cn2 = *(const float2*)&cns[n0 + 2*tg];
            float thr[4];
            #pragma unroll
            for (int lr=0; lr<4; ++lr) thr[lr] = runmin[lr] + DELTA;

            float acc[2][4] = {{0,0,0,0},{0,0,0,0}};
            #pragma unroll
            for (int ks=0; ks<4; ++ks){
                uint32_t b0 = *(const uint32_t*)(Bs + (n0+g)*72 + ks*16 + 2*tg);
                uint32_t b1 = *(const uint32_t*)(Bs + (n0+g)*72 + ks*16 + 2*tg + 8);
                #pragma unroll
                for (int mt=0; mt<2; ++mt){
                    asm volatile(
                        "mma.sync.aligned.m16n8k16.row.col.f32.bf16.bf16.f32 "
                        "{%0,%1,%2,%3}, {%4,%5,%6,%7}, {%8,%9}, {%0,%1,%2,%3};"
                        : "+f"(acc[mt][0]),"+f"(acc[mt][1]),"+f"(acc[mt][2]),"+f"(acc[mt][3])
                        : "r"(afr[mt][ks][0]),"r"(afr[mt][ks][1]),"r"(afr[mt][ks][2]),"r"(afr[mt][ks][3]),
                          "r"(b0),"r"(b1));
                }
            }
            #pragma unroll
            for (int mt=0; mt<2; ++mt)
                #pragma unroll
                for (int j=0; j<4; ++j){
                    int lr = mt*2 + (j>>1);
                    float cnv = (j&1) ? cn2.y : cn2.x;
                    float s = fmaf(-2.0f, acc[mt][j], cnv);
                    if (s < thr[lr]){
                        int k = ch*256 + n0 + 2*tg + (j&1);
                        if (cnt < CAP) cdL[tid*CAP + cnt] = (uint16_t)((lr<<10) | k);
                        cnt++;
                    }
                    runmin[lr] = fminf(runmin[lr], s);
                }
            if (nt & 1){
                #pragma unroll
                for (int lr=0; lr<4; ++lr){
                    float v = runmin[lr];
                    v = fminf(v, __shfl_xor_sync(0xffffffffu, v, 1));
                    v = fminf(v, __shfl_xor_sync(0xffffffffu, v, 2));
                    runmin[lr] = v;
                }
            }
        }
        __syncthreads();
    }

    // ---- per-lane exact rescore (R1 numerics), packed (score|k) min ----
    unsigned long long best[4] = {~0ull,~0ull,~0ull,~0ull};
    float xnv[4];
    #pragma unroll
    for (int lr=0; lr<4; ++lr) xnv[lr] = xns[R[lr]];

    if (cnt <= CAP){
        for (int i=0; i<cnt; ++i){
            int e = cdL[tid*CAP+i];
            int lr = e>>10, k = e & 1023;
            const float4* cr = (const float4*)(cb + k*DIM);
            float dot = 0.0f;
            #pragma unroll
            for (int q=0; q<16; ++q){
                float4 c = __ldg(cr+q);
                int d0 = q*4, rw = R[lr];
                dot = fmaf(xs[d0*128+rw],     c.x, dot);
                dot = fmaf(xs[(d0+1)*128+rw], c.y, dot);
                dot = fmaf(xs[(d0+2)*128+rw], c.z, dot);
                dot = fmaf(xs[(d0+3)*128+rw], c.w, dot);
            }
            float sc = __fsub_rn(__fadd_rn(xnv[lr], __ldg(&g_cnorm[k])), __fmul_rn(2.0f, dot));
            unsigned long long p = ((unsigned long long)f2o(sc)<<32) | (unsigned)k;
            if (p < best[lr]) best[lr] = p;
        }
    } else {
        // overflow fallback: exact-scan this lane's own 128-k slice for all 4 rows
        for (int ch2=0; ch2<4; ++ch2)
            for (int nt=0; nt<16; ++nt)
                #pragma unroll
                for (int e2=0; e2<2; ++e2){
                    int k = ch2*256 + nhalf*128 + nt*8 + 2*tg + e2;
                    const float4* cr = (const float4*)(cb + k*DIM);
                    float dot[4] = {0,0,0,0};
                    #pragma unroll
                    for (int q=0; q<16; ++q){
                        float4 c = __ldg(cr+q);
                        int d0 = q*4;
                        #pragma unroll
                        for (int lr=0; lr<4; ++lr){
                            int rw = R[lr];
                            dot[lr] = fmaf(xs[d0*128+rw],     c.x, dot[lr]);
                            dot[lr] = fmaf(xs[(d0+1)*128+rw], c.y, dot[lr]);
                            dot[lr] = fmaf(xs[(d0+2)*128+rw], c.z, dot[lr]);
                            dot[lr] = fmaf(xs[(d0+3)*128+rw], c.w, dot[lr]);
                        }
                    }
                    float cnk = __ldg(&g_cnorm[k]);
                    #pragma unroll
                    for (int lr=0; lr<4; ++lr){
                        float sc = __fsub_rn(__fadd_rn(xnv[lr], cnk), __fmul_rn(2.0f, dot[lr]));
                        unsigned long long p = ((unsigned long long)f2o(sc)<<32) | (unsigned)k;
                        if (p < best[lr]) best[lr] = p;
                    }
                }
    }

    // quad reduce (lanes tg=0..3 hold same rows) then per-(row,half) smem
    #pragma unroll
    for (int lr=0; lr<4; ++lr){
        unsigned long long v = best[lr];
        unsigned long long o = __shfl_xor_sync(0xffffffffu, v, 1); if (o<v) v=o;
        o = __shfl_xor_sync(0xffffffffu, v, 2); if (o<v) v=o;
        if (tg==0) rmn[R[lr]*2 + nhalf] = v;
    }
    __syncthreads();
    if (tid<128){
        unsigned long long a = rmn[tid*2], c2 = rmn[tid*2+1];
        sid[tid] = (int)((a<c2?a:c2) & 0x3FFull);
    }
    __syncthreads();

    // ---- straight-through output + loss (R1 elementwise rounding) ----
    float lsum = 0.0f;
    {
        int w2=tid&63, hh=(tid>>6)&1, dh=(tid>>7)*32, m=hh*64+w2;
        int k = sid[m];
        const float* cr = cb + k*DIM;
        float* ob = out + (size_t)b*DIM*HW + (size_t)(h0+hh)*64 + w2;
        #pragma unroll
        for (int i=0;i<32;i++){
            int d=dh+i;
            float q = __ldg(cr+d), xv = xs[d*128+m];
            float df = __fsub_rn(q, xv);
            lsum = __fadd_rn(lsum, __fmul_rn(df, df));
            ob[(size_t)d*HW] = __fadd_rn(xv, df);
        }
    }
    lrd[tid] = lsum;
    __syncthreads();
    #pragma unroll
    for (int s2=128; s2>0; s2>>=1){
        if (tid<s2) lrd[tid] = __fadd_rn(lrd[tid], lrd[tid+s2]);
        __syncthreads();
    }
    if (tid==0) atomicAdd(loss_ptr, lrd[0] * (1.25f/(float)QELEMS));
}

extern "C" void kernel_launch(void* const* d_in, const int* in_sizes, int n_in,
                              void* d_out, int out_size) {
    const float* x  = (const float*)d_in[0];
    const float* cb = (const float*)d_in[1];
    float* out = (float*)d_out;
    float* loss_ptr = out + (out_size - 1);

    cudaFuncSetAttribute(vq_hmma_kernel, cudaFuncAttributeMaxDynamicSharedMemorySize, SMEM_BYTES);
    vq_prep<<<4, 256>>>(cb, loss_ptr);
    vq_hmma_kernel<<<512, 256, SMEM_BYTES>>>(x, cb, out, loss_ptr);
}

// round 7
// speedup vs baseline: 1.3247x; 1.3247x over previous
#include <cuda_runtime.h>
#include <cuda_bf16.h>
#include <stdint.h>

#define KTOT 1024
#define DIM  64
#define HW   4096
#define QELEMS 4194304
#define DELTA 2.5e-3f
#define CAP  24
#define INF __int_as_float(0x7f800000)

// dynamic smem offsets (bytes)
#define XS_OFF 0        // f32 xs[64][64]               16384
#define B_OFF  16384    // bf16 B[256][72] padded       36864
#define CN_OFF 53248    // f32 cn[256]                   1024
#define CD_OFF 54272    // u16 cdL[256][CAP]            12288
#define XN_OFF 66560    // f32 xn[64]                     256
#define RM_OFF 66816    // u64 rmn[64][2]                1024
#define SI_OFF 67840    // i32 sid[64]                    256
#define LR_OFF 68096    // f32 lred[256]                 1024
#define SMEM_BYTES 69120

__device__ float g_cnorm[KTOT];
__device__ __align__(16) __nv_bfloat16 g_cbb[KTOT*DIM];

__global__ void vq_prep(const float* __restrict__ cb, float* __restrict__ loss_ptr){
    int k = blockIdx.x*256 + threadIdx.x;
    if (k==0) *loss_ptr = 0.0f;
    if (k < KTOT){
        float s = 0.0f;
        #pragma unroll
        for (int d=0; d<DIM; ++d){
            float c = cb[k*DIM+d];
            g_cbb[k*DIM+d] = __float2bfloat16(c);
            s = __fadd_rn(s, __fmul_rn(c,c));
        }
        g_cnorm[k] = s;
    }
}

__device__ __forceinline__ uint32_t packbf(float lo, float hi){
    __nv_bfloat162 h = __floats2bfloat162_rn(lo, hi);
    return *(uint32_t*)&h;
}
__device__ __forceinline__ uint32_t f2o(float f){
    uint32_t u = __float_as_uint(f);
    return (u & 0x80000000u) ? ~u : (u | 0x80000000u);
}
#define HMMA(acc,a,b0,b1) asm volatile( \
    "mma.sync.aligned.m16n8k16.row.col.f32.bf16.bf16.f32 " \
    "{%0,%1,%2,%3}, {%4,%5,%6,%7}, {%8,%9}, {%0,%1,%2,%3};" \
    : "+f"((acc)[0]),"+f"((acc)[1]),"+f"((acc)[2]),"+f"((acc)[3]) \
    : "r"((a)[0]),"r"((a)[1]),"r"((a)[2]),"r"((a)[3]), "r"(b0),"r"(b1))

__global__ void __launch_bounds__(256,3) vq_hmma_kernel(
    const float* __restrict__ x, const float* __restrict__ cb,
    float* __restrict__ out, float* __restrict__ loss_ptr)
{
    extern __shared__ char smc[];
    float*              xs  = (float*)(smc + XS_OFF);
    __nv_bfloat16*      Bs  = (__nv_bfloat16*)(smc + B_OFF);
    float*              cns = (float*)(smc + CN_OFF);
    uint16_t*           cdL = (uint16_t*)(smc + CD_OFF);
    float*              xns = (float*)(smc + XN_OFF);
    unsigned long long* rmn = (unsigned long long*)(smc + RM_OFF);
    int*                sid = (int*)(smc + SI_OFF);
    float*              lrd = (float*)(smc + LR_OFF);

    const int tid = threadIdx.x;
    const int b = blockIdx.x>>6, h = blockIdx.x&63;

    // ---- load x tile [64d][64w] (coalesced over w) ----
    {
        int w2 = tid&63, d0 = tid>>6;
        const float* xb = x + (size_t)b*DIM*HW + (size_t)h*64 + w2;
        #pragma unroll
        for (int i=0;i<16;i++){ int d = d0*16+i; xs[d*64+w2] = xb[(size_t)d*HW]; }
    }
    __syncthreads();

    // ---- per-row ||x||^2 (mul/add, ascending d) ----
    if (tid<64){
        float s=0.0f;
        #pragma unroll
        for (int d=0; d<DIM; ++d){ float v=xs[d*64+tid]; s=__fadd_rn(s,__fmul_rn(v,v)); }
        xns[tid]=s;
    }

    const int lane = tid&31, w = tid>>5;
    const int g = lane>>2, tg = lane&3;
    const int mbase = (w&3)*16, nh = w>>2;   // 4 m-quarters x 2 n-halves
    const int R0 = mbase+g, R1 = R0+8;

    // ---- A fragments (one m16 tile per warp, m16n8k16 row-major) ----
    uint32_t afr[4][4];
    #pragma unroll
    for (int ks=0; ks<4; ++ks){
        int c0 = ks*16 + 2*tg, c2 = c0 + 8;
        afr[ks][0] = packbf(xs[c0*64+R0], xs[(c0+1)*64+R0]);
        afr[ks][1] = packbf(xs[c0*64+R1], xs[(c0+1)*64+R1]);
        afr[ks][2] = packbf(xs[c2*64+R0], xs[(c2+1)*64+R0]);
        afr[ks][3] = packbf(xs[c2*64+R1], xs[(c2+1)*64+R1]);
    }

    float rm0 = INF, rm1 = INF;
    int cnt = 0;

    for (int ch=0; ch<4; ++ch){
        // ---- stage B chunk (256k x 64d bf16 = 2048 uint4) + cn ----
        {
            const uint4* src = ((const uint4*)g_cbb) + ch*2048;
            #pragma unroll
            for (int j=tid; j<2048; j+=256){
                int row=j>>3, part=j&7;
                *(uint4*)(Bs + row*72 + part*8) = src[j];
            }
            cns[tid] = g_cnorm[ch*256+tid];
        }
        __syncthreads();

        #pragma unroll 1
        for (int it=0; it<8; ++it){
            int n0 = nh*128 + it*16;            // two n8 tiles: n0, n0+8
            float2 cnA = *(const float2*)&cns[n0 + 2*tg];
            float2 cnB = *(const float2*)&cns[n0 + 8 + 2*tg];

            float accA[4] = {0,0,0,0}, accB[4] = {0,0,0,0};
            #pragma unroll
            for (int ks=0; ks<4; ++ks){
                const __nv_bfloat16* ba = Bs + (n0+g)*72   + ks*16 + 2*tg;
                const __nv_bfloat16* bb = Bs + (n0+8+g)*72 + ks*16 + 2*tg;
                uint32_t b0A = *(const uint32_t*)ba, b1A = *(const uint32_t*)(ba+8);
                uint32_t b0B = *(const uint32_t*)bb, b1B = *(const uint32_t*)(bb+8);
                HMMA(accA, afr[ks], b0A, b1A);
                HMMA(accB, afr[ks], b0B, b1B);
            }
            float sA[4], sB[4];
            #pragma unroll
            for (int j=0; j<4; ++j){
                sA[j] = fmaf(-2.0f, accA[j], (j&1)?cnA.y:cnA.x);
                sB[j] = fmaf(-2.0f, accB[j], (j&1)?cnB.y:cnB.x);
            }
            // update running min FIRST (kills the INF-window junk candidates)
            rm0 = fminf(rm0, fminf(fminf(sA[0],sA[1]), fminf(sB[0],sB[1])));
            rm1 = fminf(rm1, fminf(fminf(sA[2],sA[3]), fminf(sB[2],sB[3])));
            float t0 = rm0 + DELTA, t1 = rm1 + DELTA;
            #pragma unroll
            for (int j=0; j<4; ++j){
                int lr = j>>1;
                float thr = lr ? t1 : t0;
                if (sA[j] < thr){
                    int k = ch*256 + n0 + 2*tg + (j&1);
                    if (cnt < CAP) cdL[tid*CAP + cnt] = (uint16_t)((lr<<10) | k);
                    cnt++;
                }
                if (sB[j] < thr){
                    int k = ch*256 + n0 + 8 + 2*tg + (j&1);
                    if (cnt < CAP) cdL[tid*CAP + cnt] = (uint16_t)((lr<<10) | k);
                    cnt++;
                }
            }
        }
        __syncthreads();   // B consumed before next chunk overwrite
        // share min across the quad (lanes tg=0..3 cover the same rows)
        rm0 = fminf(rm0, __shfl_xor_sync(0xffffffffu, rm0, 1));
        rm0 = fminf(rm0, __shfl_xor_sync(0xffffffffu, rm0, 2));
        rm1 = fminf(rm1, __shfl_xor_sync(0xffffffffu, rm1, 1));
        rm1 = fminf(rm1, __shfl_xor_sync(0xffffffffu, rm1, 2));
    }

    // ---- per-lane exact rescore (R1 numerics), packed (score|k) min ----
    unsigned long long best[2] = {~0ull, ~0ull};
    float xnv[2] = { xns[R0], xns[R1] };
    const int RR[2] = { R0, R1 };

    if (cnt <= CAP){
        for (int i=0; i<cnt; ++i){
            int e = cdL[tid*CAP+i];
            int lr = e>>10, k = e & 1023;
            int rw = RR[lr];
            const float4* cr = (const float4*)(cb + k*DIM);
            float dot = 0.0f;
            #pragma unroll
            for (int q=0; q<16; ++q){
                float4 c = __ldg(cr+q);
                int d0 = q*4;
                dot = fmaf(xs[d0*64+rw],     c.x, dot);
                dot = fmaf(xs[(d0+1)*64+rw], c.y, dot);
                dot = fmaf(xs[(d0+2)*64+rw], c.z, dot);
                dot = fmaf(xs[(d0+3)*64+rw], c.w, dot);
            }
            float sc = __fsub_rn(__fadd_rn(xnv[lr], __ldg(&g_cnorm[k])), __fmul_rn(2.0f, dot));
            unsigned long long p = ((unsigned long long)f2o(sc)<<32) | (unsigned)k;
            if (p < best[lr]) best[lr] = p;
        }
    } else {
        // rare overflow: exact-scan this lane's own k-slice for both rows
        #pragma unroll 1
        for (int ch2=0; ch2<4; ++ch2)
            #pragma unroll 1
            for (int it=0; it<8; ++it)
                #pragma unroll
                for (int nb=0; nb<2; ++nb)
                    #pragma unroll
                    for (int e2=0; e2<2; ++e2){
                        int k = ch2*256 + nh*128 + it*16 + nb*8 + 2*tg + e2;
                        const float4* cr = (const float4*)(cb + k*DIM);
                        float dot0 = 0.0f, dot1 = 0.0f;
                        #pragma unroll
                        for (int q=0; q<16; ++q){
                            float4 c = __ldg(cr+q);
                            int d0 = q*4;
                            dot0 = fmaf(xs[d0*64+R0],     c.x, dot0);
                            dot0 = fmaf(xs[(d0+1)*64+R0], c.y, dot0);
                            dot0 = fmaf(xs[(d0+2)*64+R0], c.z, dot0);
                            dot0 = fmaf(xs[(d0+3)*64+R0], c.w, dot0);
                            dot1 = fmaf(xs[d0*64+R1],     c.x, dot1);
                            dot1 = fmaf(xs[(d0+1)*64+R1], c.y, dot1);
                            dot1 = fmaf(xs[(d0+2)*64+R1], c.z, dot1);
                            dot1 = fmaf(xs[(d0+3)*64+R1], c.w, dot1);
                        }
                        float cnk = __ldg(&g_cnorm[k]);
                        float s0 = __fsub_rn(__fadd_rn(xnv[0], cnk), __fmul_rn(2.0f, dot0));
                        float s1 = __fsub_rn(__fadd_rn(xnv[1], cnk), __fmul_rn(2.0f, dot1));
                        unsigned long long p0 = ((unsigned long long)f2o(s0)<<32) | (unsigned)k;
                        unsigned long long p1 = ((unsigned long long)f2o(s1)<<32) | (unsigned)k;
                        if (p0 < best[0]) best[0] = p0;
                        if (p1 < best[1]) best[1] = p1;
                    }
    }

    // quad reduce (lanes tg share rows), then per-(row, n-half) smem cell
    #pragma unroll
    for (int lr=0; lr<2; ++lr){
        unsigned long long v = best[lr];
        unsigned long long o = __shfl_xor_sync(0xffffffffu, v, 1); if (o<v) v=o;
        o = __shfl_xor_sync(0xffffffffu, v, 2); if (o<v) v=o;
        if (tg==0) rmn[RR[lr]*2 + nh] = v;
    }
    __syncthreads();
    if (tid<64){
        unsigned long long a = rmn[tid*2], c2 = rmn[tid*2+1];
        sid[tid] = (int)((a<c2?a:c2) & 0x3FFull);
    }
    __syncthreads();

    // ---- straight-through output + loss (R1 elementwise rounding) ----
    float lsum = 0.0f;
    {
        int w2 = tid&63, d0 = tid>>6;
        int k = sid[w2];
        const float* cr = cb + k*DIM;
        float* ob = out + (size_t)b*DIM*HW + (size_t)h*64 + w2;
        #pragma unroll
        for (int i=0;i<16;i++){
            int d = d0*16+i;
            float q = __ldg(cr+d), xv = xs[d*64+w2];
            float df = __fsub_rn(q, xv);
            lsum = __fadd_rn(lsum, __fmul_rn(df, df));
            ob[(size_t)d*HW] = __fadd_rn(xv, df);
        }
    }
    lrd[tid] = lsum;
    __syncthreads();
    #pragma unroll
    for (int s2=128; s2>0; s2>>=1){
        if (tid<s2) lrd[tid] = __fadd_rn(lrd[tid], lrd[tid+s2]);
        __syncthreads();
    }
    if (tid==0) atomicAdd(loss_ptr, lrd[0] * (1.25f/(float)QELEMS));
}

extern "C" void kernel_launch(void* const* d_in, const int* in_sizes, int n_in,
                              void* d_out, int out_size) {
    const float* x  = (const float*)d_in[0];
    const float* cb = (const float*)d_in[1];
    float* out = (float*)d_out;
    float* loss_ptr = out + (out_size - 1);

    cudaFuncSetAttribute(vq_hmma_kernel, cudaFuncAttributeMaxDynamicSharedMemorySize, SMEM_BYTES);
    vq_prep<<<4, 256>>>(cb, loss_ptr);
    vq_hmma_kernel<<<1024, 256, SMEM_BYTES>>>(x, cb, out, loss_ptr);
}